// round 4
// baseline (speedup 1.0000x reference)
#include <cuda_runtime.h>
#include <math.h>

#define B_  4
#define H_  16
#define NT  512
#define NL  512
#define E_  64
#define P_  1024
#define BH  (B_*H_)
#define PRIOR 8.0f

// ---------------- scratch (device globals: no allocation allowed) ----------------
__device__ float g_r [B_*NL*P_];   // mu / bv
__device__ float g_c1[B_*NL*P_];   // var / bv
__device__ float g_c2[B_*NL*P_];   // 8*mu / bv
__device__ float g_add[BH*NL];     // per-(bh,n) additive logit (-inf if masked)
__device__ float g_D [BH*NL*E_];   // c2 @ w_v^T + b_v^T   [bh][n][e]
__device__ float g_G [BH*NT*P_];   // (attn @ c1) * U      [bh][m][p]

// ---------------- K0: per-(b,n) precompute + reductions ----------------
__global__ __launch_bounds__(256) void k_prep(
    const float* __restrict__ mu, const float* __restrict__ logvar,
    const float* __restrict__ pi, const unsigned char* __restrict__ mask)
{
    int n = blockIdx.x, b = blockIdx.y;
    int base = (b*NL + n)*P_;
    int t = threadIdx.x;
    float s2 = 0.f, s3 = 0.f;
#pragma unroll
    for (int i = 0; i < 4; i++) {
        int p = t + i*256;
        float m  = mu[base+p];
        float v  = expf(logvar[base+p]);
        float bv = v + PRIOR;
        float inv = 1.0f / bv;
        g_r [base+p] = m * inv;
        g_c1[base+p] = v * inv;
        g_c2[base+p] = PRIOR * m * inv;
        s2 += m * m * inv;
        s3 += logf(bv);
    }
    __shared__ float red2[8], red3[8];
#pragma unroll
    for (int o = 16; o > 0; o >>= 1) {
        s2 += __shfl_down_sync(0xffffffffu, s2, o);
        s3 += __shfl_down_sync(0xffffffffu, s3, o);
    }
    if ((t & 31) == 0) { red2[t>>5] = s2; red3[t>>5] = s3; }
    __syncthreads();
    __shared__ float sbase;
    if (t == 0) {
        float a2 = 0.f, a3 = 0.f;
        for (int i = 0; i < 8; i++) { a2 += red2[i]; a3 += red3[i]; }
        float piv = pi[b*NL + n];
        float pc  = fmaxf(piv, 1.17549435e-38f);
        sbase = logf(pc) - 0.5f*a2 - 0.5f*a3;
    }
    __syncthreads();
    if (t < H_) {
        float piv = pi[b*NL + n];
        bool msk = (mask[(b*H_ + t)*NL + n] != 0) || (piv <= 0.f);
        g_add[(b*H_ + t)*NL + n] = msk ? -INFINITY : sbase;
    }
}

// ---------------- K_D: D[bh][n][e] = c2[b] @ w_v[h]^T + b_v[h]^T ----------------
// tile 128 (n) x 64 (e), K over P
__global__ __launch_bounds__(256) void k_D(
    const float* __restrict__ wv, const float* __restrict__ bvv)
{
    int bh = blockIdx.y;
    int b  = bh >> 4, h = bh & 15;
    int m0 = blockIdx.x * 128;               // n-tile
    const float* A = g_c2 + (size_t)b*NL*P_;
    const float* W = wv   + (size_t)h*E_*P_;
    __shared__ float As[16][132], Ws[16][68];
    int t = threadIdx.x, tx = t & 15, ty = t >> 4;
    float acc[8][4] = {};
    for (int k0 = 0; k0 < P_; k0 += 16) {
#pragma unroll
        for (int i = 0; i < 2; i++) {
            int idx = t + i*256, row = idx >> 2, kq = (idx & 3)*4;
            float4 v = *(const float4*)&A[(size_t)(m0+row)*P_ + k0 + kq];
            As[kq+0][row]=v.x; As[kq+1][row]=v.y; As[kq+2][row]=v.z; As[kq+3][row]=v.w;
        }
        {
            int row = t >> 2, kq = (t & 3)*4;
            float4 v = *(const float4*)&W[(size_t)row*P_ + k0 + kq];
            Ws[kq+0][row]=v.x; Ws[kq+1][row]=v.y; Ws[kq+2][row]=v.z; Ws[kq+3][row]=v.w;
        }
        __syncthreads();
#pragma unroll
        for (int kk = 0; kk < 16; kk++) {
            float a[8], w[4];
#pragma unroll
            for (int i = 0; i < 8; i++) a[i] = As[kk][ty*8 + i];
#pragma unroll
            for (int j = 0; j < 4; j++) w[j] = Ws[kk][tx*4 + j];
#pragma unroll
            for (int i = 0; i < 8; i++)
#pragma unroll
                for (int j = 0; j < 4; j++) acc[i][j] += a[i] * w[j];
        }
        __syncthreads();
    }
#pragma unroll
    for (int i = 0; i < 8; i++) {
        int n = m0 + ty*8 + i;
        float4 o;
        int e0 = tx*4;
        o.x = acc[i][0] + bvv[((size_t)h*E_ + e0+0)*NL + n];
        o.y = acc[i][1] + bvv[((size_t)h*E_ + e0+1)*NL + n];
        o.z = acc[i][2] + bvv[((size_t)h*E_ + e0+2)*NL + n];
        o.w = acc[i][3] + bvv[((size_t)h*E_ + e0+3)*NL + n];
        *(float4*)&g_D[((size_t)bh*NL + n)*E_ + e0] = o;
    }
}

// ---------------- K1: scores = U[b] @ r[b]^T + pb + add (write to attn region) --
// per b: A [8192 x 1024], Bm [512 x 1024] (both K-contiguous, NT gemm), tile 128x128x16
__global__ __launch_bounds__(256) void k_scores(
    const float* __restrict__ U, const float* __restrict__ pb,
    float* __restrict__ S)
{
    int b  = blockIdx.z;
    int m0 = blockIdx.x * 128, n0 = blockIdx.y * 128;
    const float* A  = U   + (size_t)b*8192*P_;
    const float* Bm = g_r + (size_t)b*NL*P_;
    __shared__ float As[16][132], Bs[16][132];
    int t = threadIdx.x, tx = t & 15, ty = t >> 4;
    float acc[8][8] = {};
    for (int k0 = 0; k0 < P_; k0 += 16) {
#pragma unroll
        for (int i = 0; i < 2; i++) {
            int idx = t + i*256, row = idx >> 2, kq = (idx & 3)*4;
            float4 v = *(const float4*)&A[(size_t)(m0+row)*P_ + k0 + kq];
            As[kq+0][row]=v.x; As[kq+1][row]=v.y; As[kq+2][row]=v.z; As[kq+3][row]=v.w;
        }
#pragma unroll
        for (int i = 0; i < 2; i++) {
            int idx = t + i*256, row = idx >> 2, kq = (idx & 3)*4;
            float4 v = *(const float4*)&Bm[(size_t)(n0+row)*P_ + k0 + kq];
            Bs[kq+0][row]=v.x; Bs[kq+1][row]=v.y; Bs[kq+2][row]=v.z; Bs[kq+3][row]=v.w;
        }
        __syncthreads();
#pragma unroll
        for (int kk = 0; kk < 16; kk++) {
            float a[8], bb[8];
#pragma unroll
            for (int i = 0; i < 8; i++) a[i]  = As[kk][ty*8 + i];
#pragma unroll
            for (int j = 0; j < 8; j++) bb[j] = Bs[kk][tx*8 + j];
#pragma unroll
            for (int i = 0; i < 8; i++)
#pragma unroll
                for (int j = 0; j < 8; j++) acc[i][j] += a[i] * bb[j];
        }
        __syncthreads();
    }
#pragma unroll
    for (int i = 0; i < 8; i++) {
        int gi = m0 + ty*8 + i;                     // row within b's 8192
        float pbv = pb[b*8192 + gi];
        const float* addp = g_add + ((size_t)(b*H_) + (gi >> 9))*NL + n0 + tx*8;
        float* op = S + ((size_t)(b*8192 + gi))*NL + n0 + tx*8;
        float4 a0 = *(const float4*)&addp[0];
        float4 a1 = *(const float4*)&addp[4];
        float4 o0, o1;
        o0.x = acc[i][0] + pbv + a0.x; o0.y = acc[i][1] + pbv + a0.y;
        o0.z = acc[i][2] + pbv + a0.z; o0.w = acc[i][3] + pbv + a0.w;
        o1.x = acc[i][4] + pbv + a1.x; o1.y = acc[i][5] + pbv + a1.y;
        o1.z = acc[i][6] + pbv + a1.z; o1.w = acc[i][7] + pbv + a1.w;
        *(float4*)&op[0] = o0; *(float4*)&op[4] = o1;
    }
}

// ---------------- softmax over last dim (512), in place ----------------
__global__ __launch_bounds__(128) void k_softmax(float* __restrict__ S)
{
    int row = blockIdx.x;
    float* p = S + (size_t)row * NL;
    int t = threadIdx.x;
    float x[4];
    float mx = -INFINITY;
#pragma unroll
    for (int i = 0; i < 4; i++) { x[i] = p[t + i*128]; mx = fmaxf(mx, x[i]); }
    __shared__ float smx[4], ssum[4];
#pragma unroll
    for (int o = 16; o > 0; o >>= 1) mx = fmaxf(mx, __shfl_xor_sync(0xffffffffu, mx, o));
    if ((t & 31) == 0) smx[t >> 5] = mx;
    __syncthreads();
    mx = fmaxf(fmaxf(smx[0], smx[1]), fmaxf(smx[2], smx[3]));
    float s = 0.f;
#pragma unroll
    for (int i = 0; i < 4; i++) { x[i] = expf(x[i] - mx); s += x[i]; }
#pragma unroll
    for (int o = 16; o > 0; o >>= 1) s += __shfl_xor_sync(0xffffffffu, s, o);
    if ((t & 31) == 0) ssum[t >> 5] = s;
    __syncthreads();
    s = ssum[0] + ssum[1] + ssum[2] + ssum[3];
    float inv = 1.0f / s;
#pragma unroll
    for (int i = 0; i < 4; i++) p[t + i*128] = x[i] * inv;
}

// ---------------- K2: G = (attn[b] @ c1[b]) * U  (NN gemm, 128x128x16) ----------
__global__ __launch_bounds__(256) void k_av(
    const float* __restrict__ Attn, const float* __restrict__ U)
{
    int b  = blockIdx.z;
    int m0 = blockIdx.x * 128, n0 = blockIdx.y * 128;    // n over P
    const float* A  = Attn + (size_t)b*8192*NL;
    const float* Bm = g_c1 + (size_t)b*NL*P_;
    __shared__ float As[16][132], Bs[16][132];
    int t = threadIdx.x, tx = t & 15, ty = t >> 4;
    float acc[8][8] = {};
    for (int k0 = 0; k0 < NL; k0 += 16) {
#pragma unroll
        for (int i = 0; i < 2; i++) {
            int idx = t + i*256, row = idx >> 2, kq = (idx & 3)*4;
            float4 v = *(const float4*)&A[(size_t)(m0+row)*NL + k0 + kq];
            As[kq+0][row]=v.x; As[kq+1][row]=v.y; As[kq+2][row]=v.z; As[kq+3][row]=v.w;
        }
#pragma unroll
        for (int i = 0; i < 2; i++) {
            int idx = t + i*256, row = idx >> 5, c = (idx & 31)*4;
            float4 v = *(const float4*)&Bm[(size_t)(k0+row)*P_ + n0 + c];
            *(float4*)&Bs[row][c] = v;
        }
        __syncthreads();
#pragma unroll
        for (int kk = 0; kk < 16; kk++) {
            float a[8], bb[8];
#pragma unroll
            for (int i = 0; i < 8; i++) a[i]  = As[kk][ty*8 + i];
#pragma unroll
            for (int j = 0; j < 8; j++) bb[j] = Bs[kk][tx*8 + j];
#pragma unroll
            for (int i = 0; i < 8; i++)
#pragma unroll
                for (int j = 0; j < 8; j++) acc[i][j] += a[i] * bb[j];
        }
        __syncthreads();
    }
#pragma unroll
    for (int i = 0; i < 8; i++) {
        int gm = m0 + ty*8 + i;
        size_t rowoff = ((size_t)b*8192 + gm)*P_ + n0;
#pragma unroll
        for (int j = 0; j < 8; j += 4) {
            int n = tx*8 + j;
            float4 u4 = *(const float4*)&U[rowoff + n];
            float4 o;
            o.x = acc[i][j+0]*u4.x; o.y = acc[i][j+1]*u4.y;
            o.z = acc[i][j+2]*u4.z; o.w = acc[i][j+3]*u4.w;
            *(float4*)&g_G[rowoff + n] = o;
        }
    }
}

// ---------------- K3: out = G @ w_v^T + attn @ D  (tile 128 x 64) ----------------
__global__ __launch_bounds__(256) void k_out(
    const float* __restrict__ Attn, const float* __restrict__ wv,
    float* __restrict__ Out)
{
    int bh = blockIdx.y;
    int h  = bh & 15;
    int m0 = blockIdx.x * 128;
    const float* Gp = g_G  + (size_t)bh*NT*P_;
    const float* Ap = Attn + (size_t)bh*NT*NL;
    const float* W  = wv   + (size_t)h*E_*P_;
    const float* Dp = g_D  + (size_t)bh*NL*E_;
    __shared__ float As[16][132], Bs[16][68];
    int t = threadIdx.x, tx = t & 15, ty = t >> 4;
    float acc[8][4] = {};
    // phase 1: sum over P with w_v (NT)
    for (int k0 = 0; k0 < P_; k0 += 16) {
#pragma unroll
        for (int i = 0; i < 2; i++) {
            int idx = t + i*256, row = idx >> 2, kq = (idx & 3)*4;
            float4 v = *(const float4*)&Gp[(size_t)(m0+row)*P_ + k0 + kq];
            As[kq+0][row]=v.x; As[kq+1][row]=v.y; As[kq+2][row]=v.z; As[kq+3][row]=v.w;
        }
        {
            int row = t >> 2, kq = (t & 3)*4;
            float4 v = *(const float4*)&W[(size_t)row*P_ + k0 + kq];
            Bs[kq+0][row]=v.x; Bs[kq+1][row]=v.y; Bs[kq+2][row]=v.z; Bs[kq+3][row]=v.w;
        }
        __syncthreads();
#pragma unroll
        for (int kk = 0; kk < 16; kk++) {
            float a[8], w[4];
#pragma unroll
            for (int i = 0; i < 8; i++) a[i] = As[kk][ty*8 + i];
#pragma unroll
            for (int j = 0; j < 4; j++) w[j] = Bs[kk][tx*4 + j];
#pragma unroll
            for (int i = 0; i < 8; i++)
#pragma unroll
                for (int j = 0; j < 4; j++) acc[i][j] += a[i] * w[j];
        }
        __syncthreads();
    }
    // phase 2: sum over Nl with D (NN)
    for (int k0 = 0; k0 < NL; k0 += 16) {
#pragma unroll
        for (int i = 0; i < 2; i++) {
            int idx = t + i*256, row = idx >> 2, kq = (idx & 3)*4;
            float4 v = *(const float4*)&Ap[(size_t)(m0+row)*NL + k0 + kq];
            As[kq+0][row]=v.x; As[kq+1][row]=v.y; As[kq+2][row]=v.z; As[kq+3][row]=v.w;
        }
        {
            int row = t >> 4, c = (t & 15)*4;
            float4 v = *(const float4*)&Dp[(size_t)(k0+row)*E_ + c];
            *(float4*)&Bs[row][c] = v;
        }
        __syncthreads();
#pragma unroll
        for (int kk = 0; kk < 16; kk++) {
            float a[8], w[4];
#pragma unroll
            for (int i = 0; i < 8; i++) a[i] = As[kk][ty*8 + i];
#pragma unroll
            for (int j = 0; j < 4; j++) w[j] = Bs[kk][tx*4 + j];
#pragma unroll
            for (int i = 0; i < 8; i++)
#pragma unroll
                for (int j = 0; j < 4; j++) acc[i][j] += a[i] * w[j];
        }
        __syncthreads();
    }
#pragma unroll
    for (int i = 0; i < 8; i++) {
        int m = m0 + ty*8 + i;
        float4 o;
        o.x = acc[i][0]; o.y = acc[i][1]; o.z = acc[i][2]; o.w = acc[i][3];
        *(float4*)&Out[((size_t)bh*NT + m)*E_ + tx*4] = o;
    }
}

// ---------------- launch ----------------
extern "C" void kernel_launch(void* const* d_in, const int* in_sizes, int n_in,
                              void* d_out, int out_size)
{
    const float* pu     = (const float*)d_in[0];  // [B,H,Nt,P]
    const float* pb     = (const float*)d_in[1];  // [B,H,Nt,1]
    const float* mu     = (const float*)d_in[2];  // [B,Nl,P]
    const float* logvar = (const float*)d_in[3];  // [B,Nl,P]
    const float* pi     = (const float*)d_in[4];  // [B,Nl,1]
    const float* wv     = (const float*)d_in[5];  // [H,E,P]
    const float* bvv    = (const float*)d_in[6];  // [H,E,Nl]
    const unsigned char* mask = (const unsigned char*)d_in[7]; // [B*H,1,Nl] bool

    float* out  = (float*)d_out;                  // [BH,Nt,E]
    float* attn = out + (size_t)BH*NT*E_;         // [BH,Nt,Nl]

    k_prep   <<<dim3(NL, B_),        256>>>(mu, logvar, pi, mask);
    k_D      <<<dim3(NL/128, BH),    256>>>(wv, bvv);
    k_scores <<<dim3(64, 4, B_),     256>>>(pu, pb, attn);
    k_softmax<<<BH*NT,               128>>>(attn);
    k_av     <<<dim3(64, 8, B_),     256>>>(attn, pu);
    k_out    <<<dim3(NT/128, BH),    256>>>(attn, wv, out);
}